// round 7
// baseline (speedup 1.0000x reference)
#include <cuda_runtime.h>
#include <cstdint>
#include <cstddef>

#define BM 128
#define BN 128
#define BK 8

// Scratch (alloc-free rule: __device__ globals)
static __device__ float g_Q[(size_t)8192 * 512];
static __device__ float g_V[(size_t)8192 * 512];
static __device__ float g_S[(size_t)8192 * 8192];

// ---- packed f32x2 helpers (sm_103a FFMA2 path) ----
__device__ __forceinline__ unsigned long long pack_dup(float x) {
    unsigned long long d;
    unsigned r = __float_as_uint(x);
    asm("mov.b64 %0, {%1, %1};" : "=l"(d) : "r"(r));
    return d;
}
__device__ __forceinline__ void fma2(unsigned long long& d,
                                     unsigned long long a,
                                     unsigned long long b) {
    asm("fma.rn.f32x2 %0, %1, %2, %0;" : "+l"(d) : "l"(a), "l"(b));
}
__device__ __forceinline__ float lo32(unsigned long long v) {
    return __uint_as_float((unsigned)v);
}
__device__ __forceinline__ float hi32(unsigned long long v) {
    return __uint_as_float((unsigned)(v >> 32));
}

// ---- shared 8x8 microkernel step over one k-slice ----
__device__ __forceinline__ void mk_step(const float* __restrict__ As_k,
                                        const float* __restrict__ Bs_k,
                                        int ti, int tj,
                                        unsigned long long acc[8][4]) {
    float4 a0 = *reinterpret_cast<const float4*>(As_k + ti);
    float4 a1 = *reinterpret_cast<const float4*>(As_k + ti + 4);
    ulonglong2 b0 = *reinterpret_cast<const ulonglong2*>(Bs_k + tj);
    ulonglong2 b1 = *reinterpret_cast<const ulonglong2*>(Bs_k + tj + 4);
    float a_[8] = {a0.x, a0.y, a0.z, a0.w, a1.x, a1.y, a1.z, a1.w};
#pragma unroll
    for (int i = 0; i < 8; i++) {
        unsigned long long aa = pack_dup(a_[i]);
        fma2(acc[i][0], aa, b0.x);
        fma2(acc[i][1], aa, b0.y);
        fma2(acc[i][2], aa, b1.x);
        fma2(acc[i][3], aa, b1.y);
    }
}

__device__ __forceinline__ void epilogue(float* __restrict__ C,
                                         const float* __restrict__ bias,
                                         float scale, int NN,
                                         int row0, int col0, int ti, int tj,
                                         unsigned long long acc[8][4]) {
#pragma unroll
    for (int i = 0; i < 8; i++) {
        float o[8];
#pragma unroll
        for (int j = 0; j < 4; j++) {
            o[2 * j]     = lo32(acc[i][j]);
            o[2 * j + 1] = hi32(acc[i][j]);
        }
#pragma unroll
        for (int j = 0; j < 8; j++) {
            o[j] *= scale;
            if (bias) o[j] += bias[col0 + tj + j];
        }
        float* Cp = C + (size_t)(row0 + ti + i) * NN + col0 + tj;
        *reinterpret_cast<float4*>(Cp)     = make_float4(o[0], o[1], o[2], o[3]);
        *reinterpret_cast<float4*>(Cp + 4) = make_float4(o[4], o[5], o[6], o[7]);
    }
}

// C[M,NN] = scale * (A[M,K] @ B[NN,K]^T) + bias   (both row-major)
__global__ void __launch_bounds__(256, 2)
gemm_abt(const float* __restrict__ A, const float* __restrict__ B,
         const float* __restrict__ bias, float* __restrict__ C,
         int M, int NN, int K, float scale) {
    __shared__ float As[BK][BM];
    __shared__ float Bs[BK][BN];
    const int tid  = threadIdx.x;
    const int row0 = blockIdx.y * BM;
    const int col0 = blockIdx.x * BN;
    const int lrow = tid >> 1;
    const int lk   = (tid & 1) * 4;
    const int ti   = (tid >> 4) * 8;
    const int tj   = (tid & 15) * 8;

    unsigned long long acc[8][4];
#pragma unroll
    for (int i = 0; i < 8; i++)
#pragma unroll
        for (int j = 0; j < 4; j++) acc[i][j] = 0ull;

    const float* Aptr = A + (size_t)(row0 + lrow) * K + lk;
    const float* Bptr = B + (size_t)(col0 + lrow) * K + lk;

    for (int k0 = 0; k0 < K; k0 += BK) {
        float4 av = *reinterpret_cast<const float4*>(Aptr + k0);
        float4 bv = *reinterpret_cast<const float4*>(Bptr + k0);
        __syncthreads();
        As[lk + 0][lrow] = av.x; As[lk + 1][lrow] = av.y;
        As[lk + 2][lrow] = av.z; As[lk + 3][lrow] = av.w;
        Bs[lk + 0][lrow] = bv.x; Bs[lk + 1][lrow] = bv.y;
        Bs[lk + 2][lrow] = bv.z; Bs[lk + 3][lrow] = bv.w;
        __syncthreads();
#pragma unroll
        for (int k = 0; k < BK; k++)
            mk_step(&As[k][0], &Bs[k][0], ti, tj, acc);
    }
    epilogue(C, bias, scale, NN, row0, col0, ti, tj, acc);
}

// C[M,NN] = scale * (A[M,K] @ B[K,NN])   (both row-major)
__global__ void __launch_bounds__(256, 2)
gemm_ab(const float* __restrict__ A, const float* __restrict__ B,
        const float* __restrict__ bias, float* __restrict__ C,
        int M, int NN, int K, float scale) {
    __shared__ float As[BK][BM];
    __shared__ float Bs[BK][BN];
    const int tid  = threadIdx.x;
    const int row0 = blockIdx.y * BM;
    const int col0 = blockIdx.x * BN;
    const int lrow = tid >> 1;
    const int lk   = (tid & 1) * 4;
    const int bk   = tid >> 5;        // 0..7
    const int bj   = (tid & 31) * 4;  // 0..124
    const int ti   = (tid >> 4) * 8;
    const int tj   = (tid & 15) * 8;

    unsigned long long acc[8][4];
#pragma unroll
    for (int i = 0; i < 8; i++)
#pragma unroll
        for (int j = 0; j < 4; j++) acc[i][j] = 0ull;

    const float* Aptr = A + (size_t)(row0 + lrow) * K + lk;

    for (int k0 = 0; k0 < K; k0 += BK) {
        float4 av = *reinterpret_cast<const float4*>(Aptr + k0);
        float4 bv = *reinterpret_cast<const float4*>(
            B + (size_t)(k0 + bk) * NN + col0 + bj);
        __syncthreads();
        As[lk + 0][lrow] = av.x; As[lk + 1][lrow] = av.y;
        As[lk + 2][lrow] = av.z; As[lk + 3][lrow] = av.w;
        *reinterpret_cast<float4*>(&Bs[bk][bj]) = bv;
        __syncthreads();
#pragma unroll
        for (int k = 0; k < BK; k++)
            mk_step(&As[k][0], &Bs[k][0], ti, tj, acc);
    }
    epilogue(C, bias, scale, NN, row0, col0, ti, tj, acc);
}

// In-place row softmax over 8192 columns; one CTA per row, row in registers.
__global__ void __launch_bounds__(256)
softmax_rows(float* __restrict__ S) {
    const int NN  = 8192;
    const int row = blockIdx.x;
    float* Sr = S + (size_t)row * NN;
    const int tid = threadIdx.x;

    float4 v[8];
    float m = -3.4e38f;
#pragma unroll
    for (int i = 0; i < 8; i++) {
        v[i] = *reinterpret_cast<const float4*>(Sr + i * 1024 + tid * 4);
        m = fmaxf(m, fmaxf(fmaxf(v[i].x, v[i].y), fmaxf(v[i].z, v[i].w)));
    }
#pragma unroll
    for (int o = 16; o > 0; o >>= 1)
        m = fmaxf(m, __shfl_xor_sync(0xffffffffu, m, o));

    __shared__ float red[8];
    const int wid = tid >> 5, lid = tid & 31;
    if (lid == 0) red[wid] = m;
    __syncthreads();
    float bm = red[0];
#pragma unroll
    for (int w = 1; w < 8; w++) bm = fmaxf(bm, red[w]);

    float s = 0.f;
#pragma unroll
    for (int i = 0; i < 8; i++) {
        v[i].x = __expf(v[i].x - bm);
        v[i].y = __expf(v[i].y - bm);
        v[i].z = __expf(v[i].z - bm);
        v[i].w = __expf(v[i].w - bm);
        s += v[i].x + v[i].y + v[i].z + v[i].w;
    }
#pragma unroll
    for (int o = 16; o > 0; o >>= 1)
        s += __shfl_xor_sync(0xffffffffu, s, o);

    __syncthreads();
    if (lid == 0) red[wid] = s;
    __syncthreads();
    float tot = red[0];
#pragma unroll
    for (int w = 1; w < 8; w++) tot += red[w];
    float inv = 1.0f / tot;

#pragma unroll
    for (int i = 0; i < 8; i++) {
        v[i].x *= inv; v[i].y *= inv; v[i].z *= inv; v[i].w *= inv;
        *reinterpret_cast<float4*>(Sr + i * 1024 + tid * 4) = v[i];
    }
}

extern "C" void kernel_launch(void* const* d_in, const int* in_sizes, int n_in,
                              void* d_out, int out_size) {
    const float* emb = (const float*)d_in[0];
    const float* Wqk = (const float*)d_in[1];
    const float* bqk = (const float*)d_in[2];
    const float* Wv  = (const float*)d_in[3];
    const float* bv  = (const float*)d_in[4];
    float* out = (float*)d_out;

    void *pQ, *pV, *pS;
    cudaGetSymbolAddress(&pQ, g_Q);
    cudaGetSymbolAddress(&pV, g_V);
    cudaGetSymbolAddress(&pS, g_S);
    float* Q = (float*)pQ;
    float* V = (float*)pV;
    float* S = (float*)pS;

    const int N = 8192, D = 512;
    dim3 blk(256);

    // Projections: Q = emb @ Wqk^T + bqk ; V = emb @ Wv^T + bv
    dim3 gproj(D / BN, N / BM);
    gemm_abt<<<gproj, blk>>>(emb, Wqk, bqk, Q, N, D, D, 1.0f);
    gemm_abt<<<gproj, blk>>>(emb, Wv, bv, V, N, D, D, 1.0f);

    // Scores: S = (Q @ Q^T) / sqrt(D)
    dim3 gs(N / BN, N / BM);
    gemm_abt<<<gs, blk>>>(Q, Q, nullptr, S, N, N, D, 0.0441941738241592f);

    // Row softmax in place
    softmax_rows<<<N, blk>>>(S);

    // Output: out = P @ V
    dim3 go(D / BN, N / BM);
    gemm_ab<<<go, blk>>>(S, V, nullptr, out, N, D, N, 1.0f);
}

// round 14
// speedup vs baseline: 1.8019x; 1.8019x over previous
#include <cuda_runtime.h>
#include <cuda_bf16.h>
#include <cstdint>
#include <cstddef>

#define NT 8192
#define DF 512

// ---------------- scratch (__device__ globals; no allocation) ----------------
static __device__ float          g_S [(size_t)NT * NT];
static __device__ __nv_bfloat16  g_Ph[(size_t)NT * NT];
static __device__ __nv_bfloat16  g_Pl[(size_t)NT * NT];
static __device__ float          g_Q [(size_t)NT * DF];
static __device__ float          g_Vf[(size_t)NT * DF];
static __device__ __nv_bfloat16  g_Eh[(size_t)NT * DF];
static __device__ __nv_bfloat16  g_El[(size_t)NT * DF];
static __device__ __nv_bfloat16  g_Qh[(size_t)NT * DF];
static __device__ __nv_bfloat16  g_Ql[(size_t)NT * DF];
static __device__ __nv_bfloat16  g_Vth[(size_t)DF * NT];
static __device__ __nv_bfloat16  g_Vtl[(size_t)DF * NT];
static __device__ __nv_bfloat16  g_Wqh[DF * DF], g_Wql[DF * DF];
static __device__ __nv_bfloat16  g_Wvh[DF * DF], g_Wvl[DF * DF];

// ---------------- helpers ----------------
__device__ __forceinline__ uint32_t smem_u32(const void* p) {
    uint32_t a;
    asm("{ .reg .u64 t; cvta.to.shared.u64 t, %1; cvt.u32.u64 %0, t; }"
        : "=r"(a) : "l"(p));
    return a;
}
__device__ __forceinline__ void cp_async16(uint32_t dst, const void* src) {
    asm volatile("cp.async.cg.shared.global [%0], [%1], 16;"
                 :: "r"(dst), "l"(src) : "memory");
}
__device__ __forceinline__ void ldm_x4(uint32_t* r, uint32_t addr) {
    asm volatile("ldmatrix.sync.aligned.m8n8.x4.shared.b16 {%0,%1,%2,%3}, [%4];"
                 : "=r"(r[0]), "=r"(r[1]), "=r"(r[2]), "=r"(r[3]) : "r"(addr));
}
__device__ __forceinline__ void mma16816(float* c, const uint32_t* a,
                                         uint32_t b0, uint32_t b1) {
    asm volatile(
        "mma.sync.aligned.m16n8k16.row.col.f32.bf16.bf16.f32 "
        "{%0,%1,%2,%3}, {%4,%5,%6,%7}, {%8,%9}, {%0,%1,%2,%3};"
        : "+f"(c[0]), "+f"(c[1]), "+f"(c[2]), "+f"(c[3])
        : "r"(a[0]), "r"(a[1]), "r"(a[2]), "r"(a[3]), "r"(b0), "r"(b1));
}

// =====================================================================
// C[M,NN] (fp32) = scale * (A @ B^T) + bias, 3-pass split-bf16 via HMMA.
// A: (Ah,Al) [Mtot,Kpass] bf16 row-major; B: (Bh,Bl) [Ntot,Kpass] bf16.
// CTA tile 128x128, 8 warps (warp tile 32x64), BK=32, cp.async dbl-buffer.
// Smem rows padded to 80B: 80 mod 128 cycles all 8 phases -> conflict-free
// ldmatrix without XOR swizzle.
// =====================================================================
#define ROWB 80
#define TILE_B (128 * ROWB)          // 10240 B per operand tile

__global__ void __launch_bounds__(256, 2)
mma_gemm(const __nv_bfloat16* __restrict__ Ah, const __nv_bfloat16* __restrict__ Al,
         int lda,
         const __nv_bfloat16* __restrict__ Bh, const __nv_bfloat16* __restrict__ Bl,
         int ldb,
         const float* __restrict__ bias, float* __restrict__ C, int ldc,
         int Kpass, float scale) {
    __shared__ __align__(16) char sm[4 * TILE_B];   // A0 B0 A1 B1
    const uint32_t sbase = smem_u32(sm);

    const int tid  = threadIdx.x;
    const int lane = tid & 31;
    const int w    = tid >> 5;
    const int wm   = w >> 1;                 // 0..3  -> rows wm*32
    const int wn   = w & 1;                  // 0..1  -> cols wn*64
    const int row0 = blockIdx.y * 128;
    const int col0 = blockIdx.x * 128;

    // loader mapping: 4 granules of 16B per thread (2 for A, 2 for B)
    const int lrow = tid >> 1;               // 0..127 (two granule-cols each)
    const int lcol = (tid & 1) * 2;          // granule col 0/1 or 2/3

    const int cpp = Kpass >> 5;              // 32-wide chunks per pass
    const int NC  = 3 * cpp;

    float acc[2][8][4];
#pragma unroll
    for (int i = 0; i < 2; i++)
#pragma unroll
        for (int j = 0; j < 8; j++)
#pragma unroll
            for (int q = 0; q < 4; q++) acc[i][j][q] = 0.f;

    // ---- per-chunk tile load (cp.async) ----
    auto load_tile = [&](int c, int buf) {
        const int p  = c / cpp;
        const int kc = (c - p * cpp) << 5;
        const __nv_bfloat16* Aop = (p < 2)  ? Ah : Al;
        const __nv_bfloat16* Bop = (p == 1) ? Bl : Bh;
        const __nv_bfloat16* Ag = Aop + (size_t)(row0 + lrow) * lda + kc + lcol * 8;
        const __nv_bfloat16* Bg = Bop + (size_t)(col0 + lrow) * ldb + kc + lcol * 8;
        uint32_t dA = sbase + buf * 2 * TILE_B + (uint32_t)lrow * ROWB + lcol * 16;
        uint32_t dB = dA + TILE_B;
        cp_async16(dA,      Ag);
        cp_async16(dA + 16, Ag + 8);
        cp_async16(dB,      Bg);
        cp_async16(dB + 16, Bg + 8);
    };

    load_tile(0, 0);
    asm volatile("cp.async.commit_group;" ::: "memory");

    for (int c = 0; c < NC; c++) {
        const int buf = c & 1;
        if (c + 1 < NC) {
            load_tile(c + 1, buf ^ 1);
            asm volatile("cp.async.commit_group;" ::: "memory");
            asm volatile("cp.async.wait_group 1;" ::: "memory");
        } else {
            asm volatile("cp.async.wait_group 0;" ::: "memory");
        }
        __syncthreads();

        const uint32_t bA = sbase + buf * 2 * TILE_B;
        const uint32_t bB = bA + TILE_B;
#pragma unroll
        for (int ks = 0; ks < 2; ks++) {
            uint32_t a[2][4], b[4][4];
#pragma unroll
            for (int i = 0; i < 2; i++) {
                uint32_t addr = bA +
                    (uint32_t)(wm * 32 + i * 16 + (lane & 15)) * ROWB +
                    ks * 32 + (lane >> 4) * 16;
                ldm_x4(a[i], addr);
            }
#pragma unroll
            for (int j2 = 0; j2 < 4; j2++) {
                uint32_t addr = bB +
                    (uint32_t)(wn * 64 + j2 * 16 + ((lane >> 4) & 1) * 8 + (lane & 7)) * ROWB +
                    ks * 32 + ((lane >> 3) & 1) * 16;
                ldm_x4(b[j2], addr);
            }
#pragma unroll
            for (int i = 0; i < 2; i++)
#pragma unroll
                for (int j = 0; j < 8; j++)
                    mma16816(acc[i][j], a[i], b[j >> 1][(j & 1) * 2],
                             b[j >> 1][(j & 1) * 2 + 1]);
        }
        __syncthreads();
    }

    // ---- epilogue ----
    const int er = lane >> 2;          // 0..7
    const int ec = (lane & 3) * 2;     // 0,2,4,6
#pragma unroll
    for (int i = 0; i < 2; i++) {
#pragma unroll
        for (int j = 0; j < 8; j++) {
            const int col = col0 + wn * 64 + j * 8 + ec;
            float b0 = bias ? bias[col]     : 0.f;
            float b1 = bias ? bias[col + 1] : 0.f;
            const int r_hi = row0 + wm * 32 + i * 16 + er;
            float2 v0 = make_float2(acc[i][j][0] * scale + b0,
                                    acc[i][j][1] * scale + b1);
            float2 v1 = make_float2(acc[i][j][2] * scale + b0,
                                    acc[i][j][3] * scale + b1);
            *reinterpret_cast<float2*>(C + (size_t)r_hi * ldc + col)       = v0;
            *reinterpret_cast<float2*>(C + (size_t)(r_hi + 8) * ldc + col) = v1;
        }
    }
}

// ---------------- split fp32 -> (hi, lo) bf16 ----------------
__device__ __forceinline__ void split1(float x, __nv_bfloat16& h, __nv_bfloat16& l) {
    h = __float2bfloat16_rn(x);
    l = __float2bfloat16_rn(x - __bfloat162float(h));
}
__device__ __forceinline__ unsigned pack2(__nv_bfloat16 a, __nv_bfloat16 b) {
    __nv_bfloat162 v(a, b);
    return *reinterpret_cast<unsigned*>(&v);
}

__global__ void __launch_bounds__(256)
split_pair(const float* __restrict__ x, __nv_bfloat16* __restrict__ hi,
           __nv_bfloat16* __restrict__ lo, int n4) {
    int i = blockIdx.x * 256 + threadIdx.x;
    if (i >= n4) return;
    float4 v = reinterpret_cast<const float4*>(x)[i];
    __nv_bfloat16 h0, l0, h1, l1, h2, l2, h3, l3;
    split1(v.x, h0, l0); split1(v.y, h1, l1);
    split1(v.z, h2, l2); split1(v.w, h3, l3);
    reinterpret_cast<uint2*>(hi)[i] = make_uint2(pack2(h0, h1), pack2(h2, h3));
    reinterpret_cast<uint2*>(lo)[i] = make_uint2(pack2(l0, l1), pack2(l2, l3));
}

// ---------------- V [NT, DF] fp32 -> Vt hi/lo [DF, NT] bf16 ----------------
__global__ void __launch_bounds__(256)
transpose_split(const float* __restrict__ V, __nv_bfloat16* __restrict__ Th,
                __nv_bfloat16* __restrict__ Tl) {
    __shared__ float t[32][33];
    const int tx = threadIdx.x, ty = threadIdx.y;   // block (32, 8)
    const int bx = blockIdx.x;                      // d tile
    const int by = blockIdx.y;                      // n tile
#pragma unroll
    for (int j = 0; j < 4; j++)
        t[ty + 8 * j][tx] = V[(size_t)(by * 32 + ty + 8 * j) * DF + bx * 32 + tx];
    __syncthreads();
#pragma unroll
    for (int j = 0; j < 4; j++) {
        float v = t[tx][ty + 8 * j];
        __nv_bfloat16 h, l;
        split1(v, h, l);
        size_t o = (size_t)(bx * 32 + ty + 8 * j) * NT + by * 32 + tx;
        Th[o] = h; Tl[o] = l;
    }
}

// ---------------- row softmax of S, emitting bf16 hi/lo P ----------------
__global__ void __launch_bounds__(256)
softmax_split(const float* __restrict__ S, __nv_bfloat16* __restrict__ Ph,
              __nv_bfloat16* __restrict__ Pl) {
    const int row = blockIdx.x;
    const float* Sr = S + (size_t)row * NT;
    const int tid = threadIdx.x;

    float4 v[8];
    float m = -3.4e38f;
#pragma unroll
    for (int i = 0; i < 8; i++) {
        v[i] = *reinterpret_cast<const float4*>(Sr + i * 1024 + tid * 4);
        m = fmaxf(m, fmaxf(fmaxf(v[i].x, v[i].y), fmaxf(v[i].z, v[i].w)));
    }
#pragma unroll
    for (int o = 16; o > 0; o >>= 1)
        m = fmaxf(m, __shfl_xor_sync(0xffffffffu, m, o));

    __shared__ float red[8];
    const int wid = tid >> 5, lid = tid & 31;
    if (lid == 0) red[wid] = m;
    __syncthreads();
    float bm = red[0];
#pragma unroll
    for (int w = 1; w < 8; w++) bm = fmaxf(bm, red[w]);

    float s = 0.f;
#pragma unroll
    for (int i = 0; i < 8; i++) {
        v[i].x = __expf(v[i].x - bm);
        v[i].y = __expf(v[i].y - bm);
        v[i].z = __expf(v[i].z - bm);
        v[i].w = __expf(v[i].w - bm);
        s += v[i].x + v[i].y + v[i].z + v[i].w;
    }
#pragma unroll
    for (int o = 16; o > 0; o >>= 1)
        s += __shfl_xor_sync(0xffffffffu, s, o);
    __syncthreads();
    if (lid == 0) red[wid] = s;
    __syncthreads();
    float tot = red[0];
#pragma unroll
    for (int w = 1; w < 8; w++) tot += red[w];
    const float inv = 1.0f / tot;

    __nv_bfloat16* PhR = Ph + (size_t)row * NT;
    __nv_bfloat16* PlR = Pl + (size_t)row * NT;
#pragma unroll
    for (int i = 0; i < 8; i++) {
        float p0 = v[i].x * inv, p1 = v[i].y * inv, p2 = v[i].z * inv, p3 = v[i].w * inv;
        __nv_bfloat16 h0, l0, h1, l1, h2, l2, h3, l3;
        split1(p0, h0, l0); split1(p1, h1, l1);
        split1(p2, h2, l2); split1(p3, h3, l3);
        int e = i * 1024 + tid * 4;
        *reinterpret_cast<uint2*>(PhR + e) = make_uint2(pack2(h0, h1), pack2(h2, h3));
        *reinterpret_cast<uint2*>(PlR + e) = make_uint2(pack2(l0, l1), pack2(l2, l3));
    }
}

// =====================================================================
extern "C" void kernel_launch(void* const* d_in, const int* in_sizes, int n_in,
                              void* d_out, int out_size) {
    const float* emb = (const float*)d_in[0];
    const float* Wqk = (const float*)d_in[1];
    const float* bqk = (const float*)d_in[2];
    const float* Wv  = (const float*)d_in[3];
    const float* bv  = (const float*)d_in[4];
    float* out = (float*)d_out;

    void *pS, *pPh, *pPl, *pQ, *pVf, *pEh, *pEl, *pQh, *pQl, *pVth, *pVtl;
    void *pWqh, *pWql, *pWvh, *pWvl;
    cudaGetSymbolAddress(&pS,  g_S);   cudaGetSymbolAddress(&pPh, g_Ph);
    cudaGetSymbolAddress(&pPl, g_Pl);  cudaGetSymbolAddress(&pQ,  g_Q);
    cudaGetSymbolAddress(&pVf, g_Vf);  cudaGetSymbolAddress(&pEh, g_Eh);
    cudaGetSymbolAddress(&pEl, g_El);  cudaGetSymbolAddress(&pQh, g_Qh);
    cudaGetSymbolAddress(&pQl, g_Ql);  cudaGetSymbolAddress(&pVth, g_Vth);
    cudaGetSymbolAddress(&pVtl, g_Vtl);
    cudaGetSymbolAddress(&pWqh, g_Wqh); cudaGetSymbolAddress(&pWql, g_Wql);
    cudaGetSymbolAddress(&pWvh, g_Wvh); cudaGetSymbolAddress(&pWvl, g_Wvl);

    float* S = (float*)pS;
    __nv_bfloat16 *Ph = (__nv_bfloat16*)pPh, *Pl = (__nv_bfloat16*)pPl;
    float *Q = (float*)pQ, *Vf = (float*)pVf;
    __nv_bfloat16 *Eh = (__nv_bfloat16*)pEh, *El = (__nv_bfloat16*)pEl;
    __nv_bfloat16 *Qh = (__nv_bfloat16*)pQh, *Ql = (__nv_bfloat16*)pQl;
    __nv_bfloat16 *Vth = (__nv_bfloat16*)pVth, *Vtl = (__nv_bfloat16*)pVtl;
    __nv_bfloat16 *Wqh = (__nv_bfloat16*)pWqh, *Wql = (__nv_bfloat16*)pWql;
    __nv_bfloat16 *Wvh = (__nv_bfloat16*)pWvh, *Wvl = (__nv_bfloat16*)pWvl;

    const float inv_sqrt_d = 0.0441941738241592f;  // 1/sqrt(512)
    dim3 blk(256);

    // 1) split inputs to bf16 hi/lo
    split_pair<<<(NT * DF / 4 + 255) / 256, 256>>>(emb, Eh, El, NT * DF / 4);
    split_pair<<<(DF * DF / 4 + 255) / 256, 256>>>(Wqk, Wqh, Wql, DF * DF / 4);
    split_pair<<<(DF * DF / 4 + 255) / 256, 256>>>(Wv,  Wvh, Wvl, DF * DF / 4);

    // 2) projections: Q = emb@Wqk^T + bqk ; Vf = emb@Wv^T + bv
    dim3 gproj(DF / 128, NT / 128);
    mma_gemm<<<gproj, blk>>>(Eh, El, DF, Wqh, Wql, DF, bqk, Q, DF, DF, 1.0f);
    mma_gemm<<<gproj, blk>>>(Eh, El, DF, Wvh, Wvl, DF, bv, Vf, DF, DF, 1.0f);

    // 3) split Q; transpose+split V
    split_pair<<<(NT * DF / 4 + 255) / 256, 256>>>(Q, Qh, Ql, NT * DF / 4);
    transpose_split<<<dim3(DF / 32, NT / 32), dim3(32, 8)>>>(Vf, Vth, Vtl);

    // 4) S = (Q @ Q^T) / sqrt(D)
    dim3 gs(NT / 128, NT / 128);
    mma_gemm<<<gs, blk>>>(Qh, Ql, DF, Qh, Ql, DF, nullptr, S, NT, DF, inv_sqrt_d);

    // 5) row softmax -> Ph, Pl (bf16 splits)
    softmax_split<<<NT, blk>>>(S, Ph, Pl);

    // 6) out = P @ V   (= P @ Vt^T)
    dim3 go(DF / 128, NT / 128);
    mma_gemm<<<go, blk>>>(Ph, Pl, NT, Vth, Vtl, NT, nullptr, out, DF, NT, 1.0f);
}

// round 16
// speedup vs baseline: 2.4407x; 1.3545x over previous
#include <cuda_runtime.h>
#include <cuda_bf16.h>
#include <cstdint>
#include <cstddef>

#define NT 8192
#define DF 512

// ---------------- scratch (__device__ globals; no allocation) ----------------
static __device__ float          g_S [(size_t)NT * NT];
static __device__ __nv_bfloat16  g_Ph[(size_t)NT * NT];
static __device__ __nv_bfloat16  g_Pl[(size_t)NT * NT];
static __device__ float          g_Vf[(size_t)NT * DF];
static __device__ __nv_bfloat16  g_Eh[(size_t)NT * DF];
static __device__ __nv_bfloat16  g_El[(size_t)NT * DF];
static __device__ __nv_bfloat16  g_Qh[(size_t)NT * DF];
static __device__ __nv_bfloat16  g_Ql[(size_t)NT * DF];
static __device__ __nv_bfloat16  g_Vth[(size_t)DF * NT];
static __device__ __nv_bfloat16  g_Vtl[(size_t)DF * NT];
static __device__ __nv_bfloat16  g_Wqh[DF * DF], g_Wql[DF * DF];
static __device__ __nv_bfloat16  g_Wvh[DF * DF], g_Wvl[DF * DF];

// ---------------- helpers ----------------
__device__ __forceinline__ uint32_t smem_u32(const void* p) {
    uint32_t a;
    asm("{ .reg .u64 t; cvta.to.shared.u64 t, %1; cvt.u32.u64 %0, t; }"
        : "=r"(a) : "l"(p));
    return a;
}
__device__ __forceinline__ void cp_async16(uint32_t dst, const void* src) {
    asm volatile("cp.async.cg.shared.global [%0], [%1], 16;"
                 :: "r"(dst), "l"(src) : "memory");
}
__device__ __forceinline__ void ldm_x4(uint32_t* r, uint32_t addr) {
    asm volatile("ldmatrix.sync.aligned.m8n8.x4.shared.b16 {%0,%1,%2,%3}, [%4];"
                 : "=r"(r[0]), "=r"(r[1]), "=r"(r[2]), "=r"(r[3]) : "r"(addr));
}
__device__ __forceinline__ void mma16816(float* c, const uint32_t* a,
                                         uint32_t b0, uint32_t b1) {
    asm volatile(
        "mma.sync.aligned.m16n8k16.row.col.f32.bf16.bf16.f32 "
        "{%0,%1,%2,%3}, {%4,%5,%6,%7}, {%8,%9}, {%0,%1,%2,%3};"
        : "+f"(c[0]), "+f"(c[1]), "+f"(c[2]), "+f"(c[3])
        : "r"(a[0]), "r"(a[1]), "r"(a[2]), "r"(a[3]), "r"(b0), "r"(b1));
}
__device__ __forceinline__ void split1(float x, __nv_bfloat16& h, __nv_bfloat16& l) {
    h = __float2bfloat16_rn(x);
    l = __float2bfloat16_rn(x - __bfloat162float(h));
}
__device__ __forceinline__ unsigned pack2(__nv_bfloat16 a, __nv_bfloat16 b) {
    __nv_bfloat162 v(a, b);
    return *reinterpret_cast<unsigned*>(&v);
}

// =====================================================================
// 3-pass split-bf16 HMMA GEMM: C = scale * (A @ B^T) + bias
// CTA tile 128x128, 8 warps (32x64), BK=32, 4-stage cp.async ring,
// ONE __syncthreads per chunk. Rows padded to 80B (conflict-free ldmatrix).
// MODE 0: fp32 out.  MODE 1: symmetric (triangular grid, mirror write).
// MODE 2: split bf16 out (Ch=hi, Cl=lo).
// =====================================================================
#define ROWB 80
#define TILE_B (128 * ROWB)            // 10240 B per operand tile
#define STAGE_B (2 * TILE_B)           // 20480 B per stage (A+B)
#define GSMEM (4 * STAGE_B)            // 81920 B dynamic

template <int MODE>
__global__ void __launch_bounds__(256, 2)
mma_gemm_t(const __nv_bfloat16* __restrict__ Ah, const __nv_bfloat16* __restrict__ Al,
           int lda,
           const __nv_bfloat16* __restrict__ Bh, const __nv_bfloat16* __restrict__ Bl,
           int ldb,
           const float* __restrict__ bias, float* __restrict__ C,
           __nv_bfloat16* __restrict__ Ch, __nv_bfloat16* __restrict__ Cl,
           int ldc, int Kpass, float scale) {
    extern __shared__ __align__(16) char sm[];
    const uint32_t sbase = smem_u32(sm);

    const int tid  = threadIdx.x;
    const int lane = tid & 31;
    const int w    = tid >> 5;
    const int wm   = w >> 1;                 // 0..3
    const int wn   = w & 1;                  // 0..1

    int row0, col0;
    if (MODE == 1) {
        const int idx = blockIdx.x;
        float f = sqrtf(8.0f * (float)idx + 1.0f);
        int bi = (int)((f - 1.0f) * 0.5f);
        while ((bi + 1) * (bi + 2) / 2 <= idx) bi++;
        while (bi * (bi + 1) / 2 > idx) bi--;
        const int bj = idx - bi * (bi + 1) / 2;
        row0 = bi * 128;
        col0 = bj * 128;
    } else {
        row0 = blockIdx.y * 128;
        col0 = blockIdx.x * 128;
    }

    const int lrow = tid >> 1;
    const int lcol = (tid & 1) * 2;

    const int cpp = Kpass >> 5;
    const int NC  = 3 * cpp;

    float acc[2][8][4];
#pragma unroll
    for (int i = 0; i < 2; i++)
#pragma unroll
        for (int j = 0; j < 8; j++)
#pragma unroll
            for (int q = 0; q < 4; q++) acc[i][j][q] = 0.f;

    auto load_tile = [&](int c) {
        const int stage = c & 3;
        const int p  = c / cpp;
        const int kc = (c - p * cpp) << 5;
        const __nv_bfloat16* Aop = (p < 2)  ? Ah : Al;
        const __nv_bfloat16* Bop = (p == 1) ? Bl : Bh;
        const __nv_bfloat16* Ag = Aop + (size_t)(row0 + lrow) * lda + kc + lcol * 8;
        const __nv_bfloat16* Bg = Bop + (size_t)(col0 + lrow) * ldb + kc + lcol * 8;
        uint32_t dA = sbase + stage * STAGE_B + (uint32_t)lrow * ROWB + lcol * 16;
        uint32_t dB = dA + TILE_B;
        cp_async16(dA,      Ag);
        cp_async16(dA + 16, Ag + 8);
        cp_async16(dB,      Bg);
        cp_async16(dB + 16, Bg + 8);
        asm volatile("cp.async.commit_group;" ::: "memory");
    };

    load_tile(0);
    load_tile(1);
    load_tile(2);

    for (int c = 0; c < NC; c++) {
        if (c < NC - 2)      asm volatile("cp.async.wait_group 2;" ::: "memory");
        else if (c == NC - 2) asm volatile("cp.async.wait_group 1;" ::: "memory");
        else                 asm volatile("cp.async.wait_group 0;" ::: "memory");
        __syncthreads();
        if (c + 3 < NC) load_tile(c + 3);

        const uint32_t bA = sbase + (c & 3) * STAGE_B;
        const uint32_t bB = bA + TILE_B;
#pragma unroll
        for (int ks = 0; ks < 2; ks++) {
            uint32_t a[2][4], b[4][4];
#pragma unroll
            for (int i = 0; i < 2; i++) {
                uint32_t addr = bA +
                    (uint32_t)(wm * 32 + i * 16 + (lane & 15)) * ROWB +
                    ks * 32 + (lane >> 4) * 16;
                ldm_x4(a[i], addr);
            }
#pragma unroll
            for (int j2 = 0; j2 < 4; j2++) {
                uint32_t addr = bB +
                    (uint32_t)(wn * 64 + j2 * 16 + ((lane >> 4) & 1) * 8 + (lane & 7)) * ROWB +
                    ks * 32 + ((lane >> 3) & 1) * 16;
                ldm_x4(b[j2], addr);
            }
#pragma unroll
            for (int i = 0; i < 2; i++)
#pragma unroll
                for (int j = 0; j < 8; j++)
                    mma16816(acc[i][j], a[i], b[j >> 1][(j & 1) * 2],
                             b[j >> 1][(j & 1) * 2 + 1]);
        }
    }

    // ---- epilogue ----
    const int er = lane >> 2;
    const int ec = (lane & 3) * 2;
    const bool mirror = (MODE == 1) && (row0 != col0);
#pragma unroll
    for (int i = 0; i < 2; i++) {
#pragma unroll
        for (int j = 0; j < 8; j++) {
            const int col  = col0 + wn * 64 + j * 8 + ec;
            const int r_hi = row0 + wm * 32 + i * 16 + er;
            float b0 = 0.f, b1 = 0.f;
            if (bias) { b0 = bias[col]; b1 = bias[col + 1]; }
            float v00 = acc[i][j][0] * scale + b0;
            float v01 = acc[i][j][1] * scale + b1;
            float v10 = acc[i][j][2] * scale + b0;
            float v11 = acc[i][j][3] * scale + b1;

            if (MODE == 2) {
                __nv_bfloat16 h00, l00, h01, l01, h10, l10, h11, l11;
                split1(v00, h00, l00); split1(v01, h01, l01);
                split1(v10, h10, l10); split1(v11, h11, l11);
                *reinterpret_cast<unsigned*>(Ch + (size_t)r_hi * ldc + col)       = pack2(h00, h01);
                *reinterpret_cast<unsigned*>(Cl + (size_t)r_hi * ldc + col)       = pack2(l00, l01);
                *reinterpret_cast<unsigned*>(Ch + (size_t)(r_hi + 8) * ldc + col) = pack2(h10, h11);
                *reinterpret_cast<unsigned*>(Cl + (size_t)(r_hi + 8) * ldc + col) = pack2(l10, l11);
            } else {
                *reinterpret_cast<float2*>(C + (size_t)r_hi * ldc + col)       = make_float2(v00, v01);
                *reinterpret_cast<float2*>(C + (size_t)(r_hi + 8) * ldc + col) = make_float2(v10, v11);
                if (mirror) {
                    C[(size_t)col * ldc + r_hi]           = v00;
                    C[(size_t)(col + 1) * ldc + r_hi]     = v01;
                    C[(size_t)col * ldc + r_hi + 8]       = v10;
                    C[(size_t)(col + 1) * ldc + r_hi + 8] = v11;
                }
            }
        }
    }
}

// ---------------- split fp32 -> (hi, lo) bf16 ----------------
__global__ void __launch_bounds__(256)
split_pair(const float* __restrict__ x, __nv_bfloat16* __restrict__ hi,
           __nv_bfloat16* __restrict__ lo, int n4) {
    int i = blockIdx.x * 256 + threadIdx.x;
    if (i >= n4) return;
    float4 v = reinterpret_cast<const float4*>(x)[i];
    __nv_bfloat16 h0, l0, h1, l1, h2, l2, h3, l3;
    split1(v.x, h0, l0); split1(v.y, h1, l1);
    split1(v.z, h2, l2); split1(v.w, h3, l3);
    reinterpret_cast<uint2*>(hi)[i] = make_uint2(pack2(h0, h1), pack2(h2, h3));
    reinterpret_cast<uint2*>(lo)[i] = make_uint2(pack2(l0, l1), pack2(l2, l3));
}

// ---------------- V [NT, DF] fp32 -> Vt hi/lo [DF, NT] bf16 ----------------
__global__ void __launch_bounds__(256)
transpose_split(const float* __restrict__ V, __nv_bfloat16* __restrict__ Th,
                __nv_bfloat16* __restrict__ Tl) {
    __shared__ float t[32][33];
    const int tx = threadIdx.x, ty = threadIdx.y;   // block (32, 8)
    const int bx = blockIdx.x;
    const int by = blockIdx.y;
#pragma unroll
    for (int j = 0; j < 4; j++)
        t[ty + 8 * j][tx] = V[(size_t)(by * 32 + ty + 8 * j) * DF + bx * 32 + tx];
    __syncthreads();
#pragma unroll
    for (int j = 0; j < 4; j++) {
        float v = t[tx][ty + 8 * j];
        __nv_bfloat16 h, l;
        split1(v, h, l);
        size_t o = (size_t)(bx * 32 + ty + 8 * j) * NT + by * 32 + tx;
        Th[o] = h; Tl[o] = l;
    }
}

// ---------------- row softmax of S, emitting bf16 hi/lo P ----------------
__global__ void __launch_bounds__(256)
softmax_split(const float* __restrict__ S, __nv_bfloat16* __restrict__ Ph,
              __nv_bfloat16* __restrict__ Pl) {
    const int row = blockIdx.x;
    const float* Sr = S + (size_t)row * NT;
    const int tid = threadIdx.x;

    float4 v[8];
    float m = -3.4e38f;
#pragma unroll
    for (int i = 0; i < 8; i++) {
        v[i] = *reinterpret_cast<const float4*>(Sr + i * 1024 + tid * 4);
        m = fmaxf(m, fmaxf(fmaxf(v[i].x, v[i].y), fmaxf(v[i].z, v[i].w)));
    }
#pragma unroll
    for (int o = 16; o > 0; o >>= 1)
        m = fmaxf(m, __shfl_xor_sync(0xffffffffu, m, o));

    __shared__ float red[8];
    const int wid = tid >> 5, lid = tid & 31;
    if (lid == 0) red[wid] = m;
    __syncthreads();
    float bm = red[0];
#pragma unroll
    for (int w = 1; w < 8; w++) bm = fmaxf(bm, red[w]);

    float s = 0.f;
#pragma unroll
    for (int i = 0; i < 8; i++) {
        v[i].x = __expf(v[i].x - bm);
        v[i].y = __expf(v[i].y - bm);
        v[i].z = __expf(v[i].z - bm);
        v[i].w = __expf(v[i].w - bm);
        s += v[i].x + v[i].y + v[i].z + v[i].w;
    }
#pragma unroll
    for (int o = 16; o > 0; o >>= 1)
        s += __shfl_xor_sync(0xffffffffu, s, o);
    __syncthreads();
    if (lid == 0) red[wid] = s;
    __syncthreads();
    float tot = red[0];
#pragma unroll
    for (int w = 1; w < 8; w++) tot += red[w];
    const float inv = 1.0f / tot;

    __nv_bfloat16* PhR = Ph + (size_t)row * NT;
    __nv_bfloat16* PlR = Pl + (size_t)row * NT;
#pragma unroll
    for (int i = 0; i < 8; i++) {
        float p0 = v[i].x * inv, p1 = v[i].y * inv, p2 = v[i].z * inv, p3 = v[i].w * inv;
        __nv_bfloat16 h0, l0, h1, l1, h2, l2, h3, l3;
        split1(p0, h0, l0); split1(p1, h1, l1);
        split1(p2, h2, l2); split1(p3, h3, l3);
        int e = i * 1024 + tid * 4;
        *reinterpret_cast<uint2*>(PhR + e) = make_uint2(pack2(h0, h1), pack2(h2, h3));
        *reinterpret_cast<uint2*>(PlR + e) = make_uint2(pack2(l0, l1), pack2(l2, l3));
    }
}

// =====================================================================
extern "C" void kernel_launch(void* const* d_in, const int* in_sizes, int n_in,
                              void* d_out, int out_size) {
    const float* emb = (const float*)d_in[0];
    const float* Wqk = (const float*)d_in[1];
    const float* bqk = (const float*)d_in[2];
    const float* Wv  = (const float*)d_in[3];
    const float* bv  = (const float*)d_in[4];
    float* out = (float*)d_out;

    void *pS, *pPh, *pPl, *pVf, *pEh, *pEl, *pQh, *pQl, *pVth, *pVtl;
    void *pWqh, *pWql, *pWvh, *pWvl;
    cudaGetSymbolAddress(&pS,  g_S);   cudaGetSymbolAddress(&pPh, g_Ph);
    cudaGetSymbolAddress(&pPl, g_Pl);
    cudaGetSymbolAddress(&pVf, g_Vf);  cudaGetSymbolAddress(&pEh, g_Eh);
    cudaGetSymbolAddress(&pEl, g_El);  cudaGetSymbolAddress(&pQh, g_Qh);
    cudaGetSymbolAddress(&pQl, g_Ql);  cudaGetSymbolAddress(&pVth, g_Vth);
    cudaGetSymbolAddress(&pVtl, g_Vtl);
    cudaGetSymbolAddress(&pWqh, g_Wqh); cudaGetSymbolAddress(&pWql, g_Wql);
    cudaGetSymbolAddress(&pWvh, g_Wvh); cudaGetSymbolAddress(&pWvl, g_Wvl);

    float* S = (float*)pS;
    __nv_bfloat16 *Ph = (__nv_bfloat16*)pPh, *Pl = (__nv_bfloat16*)pPl;
    float* Vf = (float*)pVf;
    __nv_bfloat16 *Eh = (__nv_bfloat16*)pEh, *El = (__nv_bfloat16*)pEl;
    __nv_bfloat16 *Qh = (__nv_bfloat16*)pQh, *Ql = (__nv_bfloat16*)pQl;
    __nv_bfloat16 *Vth = (__nv_bfloat16*)pVth, *Vtl = (__nv_bfloat16*)pVtl;
    __nv_bfloat16 *Wqh = (__nv_bfloat16*)pWqh, *Wql = (__nv_bfloat16*)pWql;
    __nv_bfloat16 *Wvh = (__nv_bfloat16*)pWvh, *Wvl = (__nv_bfloat16*)pWvl;

    cudaFuncSetAttribute(mma_gemm_t<0>, cudaFuncAttributeMaxDynamicSharedMemorySize, GSMEM);
    cudaFuncSetAttribute(mma_gemm_t<1>, cudaFuncAttributeMaxDynamicSharedMemorySize, GSMEM);
    cudaFuncSetAttribute(mma_gemm_t<2>, cudaFuncAttributeMaxDynamicSharedMemorySize, GSMEM);

    const float inv_sqrt_d = 0.0441941738241592f;  // 1/sqrt(512)
    dim3 blk(256);

    // 1) split inputs to bf16 hi/lo
    split_pair<<<(NT * DF / 4 + 255) / 256, 256>>>(emb, Eh, El, NT * DF / 4);
    split_pair<<<(DF * DF / 4 + 255) / 256, 256>>>(Wqk, Wqh, Wql, DF * DF / 4);
    split_pair<<<(DF * DF / 4 + 255) / 256, 256>>>(Wv,  Wvh, Wvl, DF * DF / 4);

    // 2) projections. Q-projection writes split bf16 (Qh, Ql) directly.
    dim3 gproj(DF / 128, NT / 128);
    mma_gemm_t<2><<<gproj, blk, GSMEM>>>(Eh, El, DF, Wqh, Wql, DF,
                                         bqk, nullptr, Qh, Ql, DF, DF, 1.0f);
    mma_gemm_t<0><<<gproj, blk, GSMEM>>>(Eh, El, DF, Wvh, Wvl, DF,
                                         bv, Vf, nullptr, nullptr, DF, DF, 1.0f);

    // 3) transpose+split V
    transpose_split<<<dim3(DF / 32, NT / 32), dim3(32, 8)>>>(Vf, Vth, Vtl);

    // 4) S = (Q @ Q^T)/sqrt(D): symmetric -> lower-triangular tiles + mirror
    const int ntile = NT / 128;                    // 64
    dim3 gs(ntile * (ntile + 1) / 2);              // 2080
    mma_gemm_t<1><<<gs, blk, GSMEM>>>(Qh, Ql, DF, Qh, Ql, DF,
                                      nullptr, S, nullptr, nullptr, NT, DF, inv_sqrt_d);

    // 5) row softmax -> Ph, Pl (bf16 splits)
    softmax_split<<<NT, blk>>>(S, Ph, Pl);

    // 6) out = P @ V   (= P @ Vt^T)
    dim3 go(DF / 128, NT / 128);
    mma_gemm_t<0><<<go, blk, GSMEM>>>(Ph, Pl, NT, Vth, Vtl, NT,
                                      nullptr, out, nullptr, nullptr, DF, NT, 1.0f);
}